// round 13
// baseline (speedup 1.0000x reference)
#include <cuda_runtime.h>
#include <cuda_bf16.h>

#define NN 100000
#define NN_PAD 100096   // 1564*64
#define NE 1600000
#define NB_SCAN 196     // ceil(NN/512)

// ---------------- scratch (static device globals; no allocation) ------------
__device__ int    g_deg_in [NN];
__device__ int    g_deg_out[NN];
__device__ int    g_rowptr [NN + 1];
__device__ int    g_cursor [NN];
__device__ int    g_esrc   [NE];
__device__ float  g_bufA   [NN_PAD * 128];
__device__ float  g_bufC   [NN_PAD * 128];
__device__ float  g_buf40  [NN_PAD * 40];
__device__ int    g_bsum   [256];
__device__ int    g_boff   [256];
// dense packed weights (two planes so warp LDG.128 lanes are contiguous):
__device__ float4 g_wA0[64 * 32];
__device__ float4 g_wB0[64 * 32];
__device__ float4 g_wA1[64 * 32];
__device__ float4 g_wB1[64 * 32];
__device__ float2 g_wp2[64 * 40];   // [p][c] = (W2[2p][c], W2[2p+1][c])

// ---------------- packed f32x2 FMA ------------------------------------------
__device__ __forceinline__ unsigned long long ffma2(unsigned long long a,
                                                    unsigned long long b,
                                                    unsigned long long c) {
    unsigned long long d;
    asm("fma.rn.f32x2 %0, %1, %2, %3;" : "=l"(d) : "l"(a), "l"(b), "l"(c));
    return d;
}

// ---------------- weight pack + degree zero ---------------------------------
__global__ void k_pack_zero(const float* __restrict__ W0,
                            const float* __restrict__ W1,
                            const float* __restrict__ W2) {
    int i = blockIdx.x * blockDim.x + threadIdx.x;
    if (i < NN) { g_deg_in[i] = 0; g_deg_out[i] = 0; }
    if (i < 64 * 32) {
        int p = i >> 5, t = i & 31;
        int c0 = 4 * t;
        const float* r0 = W0 + (2 * p) * 128;
        const float* r1 = W0 + (2 * p + 1) * 128;
        g_wA0[i] = make_float4(r0[c0],     r1[c0],     r0[c0 + 1], r1[c0 + 1]);
        g_wB0[i] = make_float4(r0[c0 + 2], r1[c0 + 2], r0[c0 + 3], r1[c0 + 3]);
        r0 = W1 + (2 * p) * 128;
        r1 = W1 + (2 * p + 1) * 128;
        g_wA1[i] = make_float4(r0[c0],     r1[c0],     r0[c0 + 1], r1[c0 + 1]);
        g_wB1[i] = make_float4(r0[c0 + 2], r1[c0 + 2], r0[c0 + 3], r1[c0 + 3]);
    }
    if (i < 64 * 40) {
        int p = i / 40, c = i % 40;
        g_wp2[i] = make_float2(W2[(2 * p) * 40 + c], W2[(2 * p + 1) * 40 + c]);
    }
}

// ---------------- CSR build chain --------------------------------------------
__global__ void k_count(const int4* __restrict__ src4, const int4* __restrict__ dst4) {
    int e = blockIdx.x * blockDim.x + threadIdx.x;
    if (e < NE / 4) {
        int4 s = src4[e];
        atomicAdd(&g_deg_out[s.x], 1);
        atomicAdd(&g_deg_out[s.y], 1);
        atomicAdd(&g_deg_out[s.z], 1);
        atomicAdd(&g_deg_out[s.w], 1);
        int4 d = dst4[e];
        atomicAdd(&g_deg_in[d.x], 1);
        atomicAdd(&g_deg_in[d.y], 1);
        atomicAdd(&g_deg_in[d.z], 1);
        atomicAdd(&g_deg_in[d.w], 1);
    }
}

__global__ void k_chunksum() {
    __shared__ int s[512];
    int t = threadIdx.x;
    int i = blockIdx.x * 512 + t;
    s[t] = (i < NN) ? g_deg_in[i] : 0;
    __syncthreads();
    for (int o = 256; o > 0; o >>= 1) {
        if (t < o) s[t] += s[t + o];
        __syncthreads();
    }
    if (t == 0) g_bsum[blockIdx.x] = s[0];
}

__global__ void k_scanblocks() {   // <<<1,256>>>
    __shared__ int s[256];
    int t = threadIdx.x;
    int v = (t < NB_SCAN) ? g_bsum[t] : 0;
    s[t] = v; __syncthreads();
    for (int o = 1; o < 256; o <<= 1) {
        int add = (t >= o) ? s[t - o] : 0;
        __syncthreads();
        s[t] += add;
        __syncthreads();
    }
    g_boff[t] = s[t] - v;
    if (t == 0) g_rowptr[NN] = NE;
}

__global__ void k_scanchunks() {
    __shared__ int s[512];
    int t = threadIdx.x;
    int i = blockIdx.x * 512 + t;
    int v = (i < NN) ? g_deg_in[i] : 0;
    s[t] = v; __syncthreads();
    for (int o = 1; o < 512; o <<= 1) {
        int add = (t >= o) ? s[t - o] : 0;
        __syncthreads();
        s[t] += add;
        __syncthreads();
    }
    int val = s[t] - v + g_boff[blockIdx.x];
    if (i < NN) { g_rowptr[i] = val; g_cursor[i] = val; }
}

__global__ void k_fill(const int4* __restrict__ src4, const int4* __restrict__ dst4) {
    int e = blockIdx.x * blockDim.x + threadIdx.x;
    if (e < NE / 4) {
        int4 s = src4[e];
        int4 d = dst4[e];
        g_esrc[atomicAdd(&g_cursor[d.x], 1)] = s.x;
        g_esrc[atomicAdd(&g_cursor[d.y], 1)] = s.y;
        g_esrc[atomicAdd(&g_cursor[d.z], 1)] = s.z;
        g_esrc[atomicAdd(&g_cursor[d.w], 1)] = s.w;
    }
}

// ---------------- layer-0 GEMM: Y = (X * rsqrt(deg_out)) @ W0 ---------------
__global__ void __launch_bounds__(256, 2)
gemm128_kernel(const float* __restrict__ X,
               const float4* __restrict__ WA,
               const float4* __restrict__ WB,
               float* __restrict__ Y) {
    __shared__ float xs[64][128];
    __shared__ float ssc[64];
    const int tx = threadIdx.x, ty = threadIdx.y;
    const int row0 = blockIdx.x * 64;
    const int tid = ty * 32 + tx;

    if (tid < 64) {
        int gr = row0 + tid;
        int d = 1;
        if (gr < NN) { d = g_deg_out[gr]; if (d < 1) d = 1; }
        ssc[tid] = rsqrtf((float)d);
    }
    __syncthreads();

    for (int i = tid; i < 64 * 32; i += 256) {
        int r = i >> 5, k4 = i & 31;
        int gr = row0 + r;
        int gl = (gr < NN) ? gr : (NN - 1);
        float4 v = reinterpret_cast<const float4*>(X + (size_t)gl * 128)[k4];
        float s = ssc[r];
        v.x *= s; v.y *= s; v.z *= s; v.w *= s;
        reinterpret_cast<float4*>(&xs[r][0])[k4] = v;
    }
    __syncthreads();

    unsigned long long acc[8][4];
#pragma unroll
    for (int r = 0; r < 8; r++)
#pragma unroll
        for (int c = 0; c < 4; c++) acc[r][c] = 0ull;

    const ulonglong2* wa = reinterpret_cast<const ulonglong2*>(WA) + tx;
    const ulonglong2* wb = reinterpret_cast<const ulonglong2*>(WB) + tx;

#pragma unroll 4
    for (int q = 0; q < 32; q++) {
        ulonglong2 wa0 = wa[(2 * q) * 32];
        ulonglong2 wb0 = wb[(2 * q) * 32];
        ulonglong2 wa1 = wa[(2 * q + 1) * 32];
        ulonglong2 wb1 = wb[(2 * q + 1) * 32];
#pragma unroll
        for (int r = 0; r < 8; r++) {
            ulonglong2 xv =
                *reinterpret_cast<const ulonglong2*>(&xs[ty * 8 + r][4 * q]);
            acc[r][0] = ffma2(xv.x, wa0.x, acc[r][0]);
            acc[r][1] = ffma2(xv.x, wa0.y, acc[r][1]);
            acc[r][2] = ffma2(xv.x, wb0.x, acc[r][2]);
            acc[r][3] = ffma2(xv.x, wb0.y, acc[r][3]);
            acc[r][0] = ffma2(xv.y, wa1.x, acc[r][0]);
            acc[r][1] = ffma2(xv.y, wa1.y, acc[r][1]);
            acc[r][2] = ffma2(xv.y, wb1.x, acc[r][2]);
            acc[r][3] = ffma2(xv.y, wb1.y, acc[r][3]);
        }
    }

#pragma unroll
    for (int r = 0; r < 8; r++) {
        int gr = row0 + ty * 8 + r;
        float4 o;
        float2 f0 = *reinterpret_cast<float2*>(&acc[r][0]);
        float2 f1 = *reinterpret_cast<float2*>(&acc[r][1]);
        float2 f2 = *reinterpret_cast<float2*>(&acc[r][2]);
        float2 f3 = *reinterpret_cast<float2*>(&acc[r][3]);
        o.x = f0.x + f0.y; o.y = f1.x + f1.y;
        o.z = f2.x + f2.y; o.w = f3.x + f3.y;
        *reinterpret_cast<float4*>(Y + (size_t)gr * 128 + tx * 4) = o;
    }
}

// ---------------- shared gather phase: xs[r] = relu(agg*sin + b) * sout -----
__device__ __forceinline__ void gather_rows(const float* __restrict__ hw,
                                            const float* __restrict__ bias,
                                            float (*xs)[128],
                                            int row0, int tx, int ty) {
    float4 bb = *reinterpret_cast<const float4*>(bias + tx * 4);
#pragma unroll 1
    for (int rr = 0; rr < 8; rr++) {
        int r = ty * 8 + rr;
        int gr = row0 + r;
        float4 h = make_float4(0.f, 0.f, 0.f, 0.f);
        if (gr < NN) {
            int e0 = g_rowptr[gr], e1 = g_rowptr[gr + 1];
            float4 acc = make_float4(0.f, 0.f, 0.f, 0.f);
            for (int base = e0; base < e1; base += 32) {
                int cnt = e1 - base; if (cnt > 32) cnt = 32;
                int myi = (tx < cnt) ? g_esrc[base + tx] : 0;
                for (int j = 0; j < cnt; j++) {
                    int s = __shfl_sync(0xffffffffu, myi, j);
                    const float4 v =
                        *reinterpret_cast<const float4*>(hw + (size_t)s * 128 + tx * 4);
                    acc.x += v.x; acc.y += v.y; acc.z += v.z; acc.w += v.w;
                }
            }
            int deg = e1 - e0; if (deg < 1) deg = 1;
            float si = rsqrtf((float)deg);
            int dout = g_deg_out[gr]; if (dout < 1) dout = 1;
            float so = rsqrtf((float)dout);
            h.x = fmaxf(acc.x * si + bb.x, 0.f) * so;
            h.y = fmaxf(acc.y * si + bb.y, 0.f) * so;
            h.z = fmaxf(acc.z * si + bb.z, 0.f) * so;
            h.w = fmaxf(acc.w * si + bb.w, 0.f) * so;
        }
        *reinterpret_cast<float4*>(&xs[r][tx * 4]) = h;
    }
}

// ---------------- fused agg(+relu+scales) -> GEMM 128 -----------------------
__global__ void __launch_bounds__(256, 2)
fused_ag128_kernel(const float* __restrict__ hw,
                   const float* __restrict__ bias,
                   const float4* __restrict__ WA,
                   const float4* __restrict__ WB,
                   float* __restrict__ Y) {
    __shared__ float xs[64][128];
    const int tx = threadIdx.x, ty = threadIdx.y;
    const int row0 = blockIdx.x * 64;

    gather_rows(hw, bias, xs, row0, tx, ty);
    __syncthreads();

    unsigned long long acc[8][4];
#pragma unroll
    for (int r = 0; r < 8; r++)
#pragma unroll
        for (int c = 0; c < 4; c++) acc[r][c] = 0ull;

    const ulonglong2* wa = reinterpret_cast<const ulonglong2*>(WA) + tx;
    const ulonglong2* wb = reinterpret_cast<const ulonglong2*>(WB) + tx;

#pragma unroll 4
    for (int q = 0; q < 32; q++) {
        ulonglong2 wa0 = wa[(2 * q) * 32];
        ulonglong2 wb0 = wb[(2 * q) * 32];
        ulonglong2 wa1 = wa[(2 * q + 1) * 32];
        ulonglong2 wb1 = wb[(2 * q + 1) * 32];
#pragma unroll
        for (int r = 0; r < 8; r++) {
            ulonglong2 xv =
                *reinterpret_cast<const ulonglong2*>(&xs[ty * 8 + r][4 * q]);
            acc[r][0] = ffma2(xv.x, wa0.x, acc[r][0]);
            acc[r][1] = ffma2(xv.x, wa0.y, acc[r][1]);
            acc[r][2] = ffma2(xv.x, wb0.x, acc[r][2]);
            acc[r][3] = ffma2(xv.x, wb0.y, acc[r][3]);
            acc[r][0] = ffma2(xv.y, wa1.x, acc[r][0]);
            acc[r][1] = ffma2(xv.y, wa1.y, acc[r][1]);
            acc[r][2] = ffma2(xv.y, wb1.x, acc[r][2]);
            acc[r][3] = ffma2(xv.y, wb1.y, acc[r][3]);
        }
    }

#pragma unroll
    for (int r = 0; r < 8; r++) {
        int gr = row0 + ty * 8 + r;
        float4 o;
        float2 f0 = *reinterpret_cast<float2*>(&acc[r][0]);
        float2 f1 = *reinterpret_cast<float2*>(&acc[r][1]);
        float2 f2 = *reinterpret_cast<float2*>(&acc[r][2]);
        float2 f3 = *reinterpret_cast<float2*>(&acc[r][3]);
        o.x = f0.x + f0.y; o.y = f1.x + f1.y;
        o.z = f2.x + f2.y; o.w = f3.x + f3.y;
        *reinterpret_cast<float4*>(Y + (size_t)gr * 128 + tx * 4) = o;
    }
}

// ---------------- fused agg(+relu+scales) -> GEMM 40 ------------------------
// gemm phase: lanes 0..19 each produce cols (2tx, 2tx+1).
__global__ void __launch_bounds__(256, 2)
fused_ag40_kernel(const float* __restrict__ hw,
                  const float* __restrict__ bias,
                  const float2* __restrict__ Wp,
                  float* __restrict__ Y) {
    __shared__ float xs[64][128];
    const int tx = threadIdx.x, ty = threadIdx.y;
    const int row0 = blockIdx.x * 64;

    gather_rows(hw, bias, xs, row0, tx, ty);
    __syncthreads();

    if (tx < 20) {
        unsigned long long acc[8][2];
#pragma unroll
        for (int r = 0; r < 8; r++) { acc[r][0] = 0ull; acc[r][1] = 0ull; }

#pragma unroll 4
        for (int q = 0; q < 32; q++) {
            // k-pairs 2q and 2q+1; cols 2tx, 2tx+1
            ulonglong2 w0 = *reinterpret_cast<const ulonglong2*>(
                &Wp[(2 * q) * 40 + 2 * tx]);
            ulonglong2 w1 = *reinterpret_cast<const ulonglong2*>(
                &Wp[(2 * q + 1) * 40 + 2 * tx]);
#pragma unroll
            for (int r = 0; r < 8; r++) {
                ulonglong2 xv =
                    *reinterpret_cast<const ulonglong2*>(&xs[ty * 8 + r][4 * q]);
                acc[r][0] = ffma2(xv.x, w0.x, acc[r][0]);
                acc[r][1] = ffma2(xv.x, w0.y, acc[r][1]);
                acc[r][0] = ffma2(xv.y, w1.x, acc[r][0]);
                acc[r][1] = ffma2(xv.y, w1.y, acc[r][1]);
            }
        }

#pragma unroll
        for (int r = 0; r < 8; r++) {
            int gr = row0 + ty * 8 + r;
            float2 f0 = *reinterpret_cast<float2*>(&acc[r][0]);
            float2 f1 = *reinterpret_cast<float2*>(&acc[r][1]);
            float2 o = make_float2(f0.x + f0.y, f1.x + f1.y);
            *reinterpret_cast<float2*>(Y + (size_t)gr * 40 + 2 * tx) = o;
        }
    }
}

// ---------------- final aggregation (f40 -> out) -----------------------------
__global__ void agg40_kernel(const float* __restrict__ hw,
                             const float* __restrict__ bias,
                             float* __restrict__ out) {
    int w = (blockIdx.x * blockDim.x + threadIdx.x) >> 5;
    int lane = threadIdx.x & 31;
    if (w >= NN) return;
    int e0 = g_rowptr[w], e1 = g_rowptr[w + 1];
    float4 acc = make_float4(0.f, 0.f, 0.f, 0.f);
    for (int base = e0; base < e1; base += 32) {
        int cnt = e1 - base; if (cnt > 32) cnt = 32;
        int myi = (lane < cnt) ? g_esrc[base + lane] : 0;
        for (int j = 0; j < cnt; j++) {
            int s = __shfl_sync(0xffffffffu, myi, j);
            if (lane < 10) {
                const float4 v = *reinterpret_cast<const float4*>(hw + (size_t)s * 40 + lane * 4);
                acc.x += v.x; acc.y += v.y; acc.z += v.z; acc.w += v.w;
            }
        }
    }
    if (lane < 10) {
        int deg = e1 - e0; if (deg < 1) deg = 1;
        float sc = rsqrtf((float)deg);
        float4 bb = *reinterpret_cast<const float4*>(bias + lane * 4);
        float4 r;
        r.x = acc.x * sc + bb.x;
        r.y = acc.y * sc + bb.y;
        r.z = acc.z * sc + bb.z;
        r.w = acc.w * sc + bb.w;
        *reinterpret_cast<float4*>(out + (size_t)w * 40 + lane * 4) = r;
    }
}

// ---------------- launch ------------------------------------------------------
extern "C" void kernel_launch(void* const* d_in, const int* in_sizes, int n_in,
                              void* d_out, int out_size) {
    (void)in_sizes; (void)n_in; (void)out_size;
    const float* feat = (const float*)d_in[0];
    const int*   src  = (const int*)  d_in[1];
    const int*   dst  = (const int*)  d_in[2];
    const float* W0   = (const float*)d_in[3];
    const float* b0   = (const float*)d_in[4];
    const float* W1   = (const float*)d_in[5];
    const float* b1   = (const float*)d_in[6];
    const float* W2   = (const float*)d_in[7];
    const float* b2   = (const float*)d_in[8];
    float* out = (float*)d_out;

    float *bufA, *bufC, *buf40;
    float4 *wA0, *wB0, *wA1, *wB1;
    float2 *wp2;
    cudaGetSymbolAddress((void**)&bufA, g_bufA);
    cudaGetSymbolAddress((void**)&bufC, g_bufC);
    cudaGetSymbolAddress((void**)&buf40, g_buf40);
    cudaGetSymbolAddress((void**)&wA0, g_wA0);
    cudaGetSymbolAddress((void**)&wB0, g_wB0);
    cudaGetSymbolAddress((void**)&wA1, g_wA1);
    cudaGetSymbolAddress((void**)&wB1, g_wB1);
    cudaGetSymbolAddress((void**)&wp2, g_wp2);

    static cudaStream_t s2 = nullptr;
    static cudaEvent_t evFork = nullptr, evCSR = nullptr;
    if (s2 == nullptr) {
        cudaStreamCreateWithFlags(&s2, cudaStreamNonBlocking);
        cudaEventCreateWithFlags(&evFork, cudaEventDisableTiming);
        cudaEventCreateWithFlags(&evCSR, cudaEventDisableTiming);
    }

    const int TB = 256;
    const int G128 = (NN + 63) / 64;                // 1563
    const int AGG  = (NN * 32 + TB - 1) / TB;       // 12500
    const int E4   = (NE / 4 + TB - 1) / TB;        // 1563
    const dim3 GB(32, 8);

    // main: pack + count (gemm0 needs only deg_out)
    k_pack_zero<<<(NN + TB - 1) / TB, TB>>>(W0, W1, W2);
    k_count    <<<E4, TB>>>((const int4*)src, (const int4*)dst);
    cudaEventRecord(evFork, 0);

    // side: CSR scan + fill hide under gemm0
    cudaStreamWaitEvent(s2, evFork, 0);
    k_chunksum  <<<NB_SCAN, 512, 0, s2>>>();
    k_scanblocks<<<1, 256, 0, s2>>>();
    k_scanchunks<<<NB_SCAN, 512, 0, s2>>>();
    k_fill      <<<E4, TB, 0, s2>>>((const int4*)src, (const int4*)dst);
    cudaEventRecord(evCSR, s2);

    // main: layer-0 GEMM (feat -> A)
    gemm128_kernel<<<G128, GB>>>(feat, wA0, wB0, bufA);

    // join, then fused layers
    cudaStreamWaitEvent(0, evCSR, 0);
    fused_ag128_kernel<<<G128, GB>>>(bufA, b0, wA1, wB1, bufC);   // agg0+gemm1
    fused_ag40_kernel <<<G128, GB>>>(bufC, b1, wp2, buf40);       // agg1+gemm2
    agg40_kernel      <<<AGG, TB>>>(buf40, b2, out);              // final agg
}

// round 15
// speedup vs baseline: 1.2188x; 1.2188x over previous
#include <cuda_runtime.h>
#include <cuda_bf16.h>

#define NN 100000
#define NN_PAD 100096   // 1564*64
#define NE 1600000
#define NB_SCAN 196     // ceil(NN/512)

// ---------------- scratch (static device globals; no allocation) ------------
__device__ int    g_deg_in [NN];
__device__ int    g_deg_out[NN];
__device__ int    g_rowptr [NN + 1];
__device__ int    g_cursor [NN];
__device__ int    g_esrc   [NE];
__device__ float  g_bufA   [NN_PAD * 128];
__device__ float  g_bufB   [NN_PAD * 128];
__device__ float  g_buf40  [NN_PAD * 40];
__device__ int    g_bsum   [256];
__device__ int    g_boff   [256];
// dense packed weights (two planes so warp LDG.128 lanes are contiguous):
__device__ float4 g_wA0[64 * 32];
__device__ float4 g_wB0[64 * 32];
__device__ float4 g_wA1[64 * 32];
__device__ float4 g_wB1[64 * 32];
__device__ float2 g_wp2[64 * 40];   // [p][c] = (W2[2p][c], W2[2p+1][c])

// ---------------- packed f32x2 FMA ------------------------------------------
__device__ __forceinline__ unsigned long long ffma2(unsigned long long a,
                                                    unsigned long long b,
                                                    unsigned long long c) {
    unsigned long long d;
    asm("fma.rn.f32x2 %0, %1, %2, %3;" : "=l"(d) : "l"(a), "l"(b), "l"(c));
    return d;
}

// ---------------- weight pack + degree zero (main stream) -------------------
__global__ void k_pack_zero(const float* __restrict__ W0,
                            const float* __restrict__ W1,
                            const float* __restrict__ W2) {
    int i = blockIdx.x * blockDim.x + threadIdx.x;
    if (i < NN) { g_deg_in[i] = 0; g_deg_out[i] = 0; }
    if (i < 64 * 32) {
        int p = i >> 5, t = i & 31;
        int c0 = 4 * t;
        const float* r0 = W0 + (2 * p) * 128;
        const float* r1 = W0 + (2 * p + 1) * 128;
        g_wA0[i] = make_float4(r0[c0],     r1[c0],     r0[c0 + 1], r1[c0 + 1]);
        g_wB0[i] = make_float4(r0[c0 + 2], r1[c0 + 2], r0[c0 + 3], r1[c0 + 3]);
        r0 = W1 + (2 * p) * 128;
        r1 = W1 + (2 * p + 1) * 128;
        g_wA1[i] = make_float4(r0[c0],     r1[c0],     r0[c0 + 1], r1[c0 + 1]);
        g_wB1[i] = make_float4(r0[c0 + 2], r1[c0 + 2], r0[c0 + 3], r1[c0 + 3]);
    }
    if (i < 64 * 40) {
        int p = i / 40, c = i % 40;
        g_wp2[i] = make_float2(W2[(2 * p) * 40 + c], W2[(2 * p + 1) * 40 + c]);
    }
}

// ---------------- CSR build chain --------------------------------------------
__global__ void k_count(const int4* __restrict__ src4, const int4* __restrict__ dst4) {
    int e = blockIdx.x * blockDim.x + threadIdx.x;
    if (e < NE / 4) {
        int4 s = src4[e];
        atomicAdd(&g_deg_out[s.x], 1);
        atomicAdd(&g_deg_out[s.y], 1);
        atomicAdd(&g_deg_out[s.z], 1);
        atomicAdd(&g_deg_out[s.w], 1);
        int4 d = dst4[e];
        atomicAdd(&g_deg_in[d.x], 1);
        atomicAdd(&g_deg_in[d.y], 1);
        atomicAdd(&g_deg_in[d.z], 1);
        atomicAdd(&g_deg_in[d.w], 1);
    }
}

__global__ void k_chunksum() {
    __shared__ int s[512];
    int t = threadIdx.x;
    int i = blockIdx.x * 512 + t;
    s[t] = (i < NN) ? g_deg_in[i] : 0;
    __syncthreads();
    for (int o = 256; o > 0; o >>= 1) {
        if (t < o) s[t] += s[t + o];
        __syncthreads();
    }
    if (t == 0) g_bsum[blockIdx.x] = s[0];
}

__global__ void k_scanblocks() {   // <<<1,256>>>
    __shared__ int s[256];
    int t = threadIdx.x;
    int v = (t < NB_SCAN) ? g_bsum[t] : 0;
    s[t] = v; __syncthreads();
    for (int o = 1; o < 256; o <<= 1) {
        int add = (t >= o) ? s[t - o] : 0;
        __syncthreads();
        s[t] += add;
        __syncthreads();
    }
    g_boff[t] = s[t] - v;
    if (t == 0) g_rowptr[NN] = NE;
}

__global__ void k_scanchunks() {
    __shared__ int s[512];
    int t = threadIdx.x;
    int i = blockIdx.x * 512 + t;
    int v = (i < NN) ? g_deg_in[i] : 0;
    s[t] = v; __syncthreads();
    for (int o = 1; o < 512; o <<= 1) {
        int add = (t >= o) ? s[t - o] : 0;
        __syncthreads();
        s[t] += add;
        __syncthreads();
    }
    int val = s[t] - v + g_boff[blockIdx.x];
    if (i < NN) { g_rowptr[i] = val; g_cursor[i] = val; }
}

__global__ void k_fill(const int4* __restrict__ src4, const int4* __restrict__ dst4) {
    int e = blockIdx.x * blockDim.x + threadIdx.x;
    if (e < NE / 4) {
        int4 s = src4[e];
        int4 d = dst4[e];
        g_esrc[atomicAdd(&g_cursor[d.x], 1)] = s.x;
        g_esrc[atomicAdd(&g_cursor[d.y], 1)] = s.y;
        g_esrc[atomicAdd(&g_cursor[d.z], 1)] = s.z;
        g_esrc[atomicAdd(&g_cursor[d.w], 1)] = s.w;
    }
}

// ---------------- GEMM: Y = (X * rsqrt(max(deg_out,1))) @ W -----------------
// Block: 64 rows x 128 cols, 256 threads (32,8); thread = 8 rows x 4 cols.
// CLAMP=true for external X (feat); false for our padded buffers.
template <bool CLAMP>
__global__ void __launch_bounds__(256, 2)
gemm128_kernel(const float* __restrict__ X,
               const float4* __restrict__ WA,
               const float4* __restrict__ WB,
               float* __restrict__ Y) {
    __shared__ float xs[64][128];
    __shared__ float ssc[64];
    const int tx = threadIdx.x, ty = threadIdx.y;
    const int row0 = blockIdx.x * 64;
    const int tid = ty * 32 + tx;

    if (tid < 64) {
        int gr = row0 + tid;
        int d = 1;
        if (gr < NN) { d = g_deg_out[gr]; if (d < 1) d = 1; }
        ssc[tid] = rsqrtf((float)d);
    }
    __syncthreads();

    for (int i = tid; i < 64 * 32; i += 256) {
        int r = i >> 5, k4 = i & 31;
        int gr = row0 + r;
        int gl = CLAMP ? ((gr < NN) ? gr : (NN - 1)) : gr;
        float4 v = reinterpret_cast<const float4*>(X + (size_t)gl * 128)[k4];
        float s = ssc[r];
        v.x *= s; v.y *= s; v.z *= s; v.w *= s;
        reinterpret_cast<float4*>(&xs[r][0])[k4] = v;
    }
    __syncthreads();

    unsigned long long acc[8][4];
#pragma unroll
    for (int r = 0; r < 8; r++)
#pragma unroll
        for (int c = 0; c < 4; c++) acc[r][c] = 0ull;

    const ulonglong2* wa = reinterpret_cast<const ulonglong2*>(WA) + tx;
    const ulonglong2* wb = reinterpret_cast<const ulonglong2*>(WB) + tx;

#pragma unroll 4
    for (int q = 0; q < 32; q++) {
        ulonglong2 wa0 = wa[(2 * q) * 32];
        ulonglong2 wb0 = wb[(2 * q) * 32];
        ulonglong2 wa1 = wa[(2 * q + 1) * 32];
        ulonglong2 wb1 = wb[(2 * q + 1) * 32];
#pragma unroll
        for (int r = 0; r < 8; r++) {
            ulonglong2 xv =
                *reinterpret_cast<const ulonglong2*>(&xs[ty * 8 + r][4 * q]);
            acc[r][0] = ffma2(xv.x, wa0.x, acc[r][0]);
            acc[r][1] = ffma2(xv.x, wa0.y, acc[r][1]);
            acc[r][2] = ffma2(xv.x, wb0.x, acc[r][2]);
            acc[r][3] = ffma2(xv.x, wb0.y, acc[r][3]);
            acc[r][0] = ffma2(xv.y, wa1.x, acc[r][0]);
            acc[r][1] = ffma2(xv.y, wa1.y, acc[r][1]);
            acc[r][2] = ffma2(xv.y, wb1.x, acc[r][2]);
            acc[r][3] = ffma2(xv.y, wb1.y, acc[r][3]);
        }
    }

#pragma unroll
    for (int r = 0; r < 8; r++) {
        int gr = row0 + ty * 8 + r;
        float4 o;
        float2 f0 = *reinterpret_cast<float2*>(&acc[r][0]);
        float2 f1 = *reinterpret_cast<float2*>(&acc[r][1]);
        float2 f2 = *reinterpret_cast<float2*>(&acc[r][2]);
        float2 f3 = *reinterpret_cast<float2*>(&acc[r][3]);
        o.x = f0.x + f0.y; o.y = f1.x + f1.y;
        o.z = f2.x + f2.y; o.w = f3.x + f3.y;
        *reinterpret_cast<float4*>(Y + (size_t)gr * 128 + tx * 4) = o;
    }
}

// 40-col version (X is our padded buffer; no bounds checks).
__global__ void gemm40_kernel(const float* __restrict__ X,
                              const float2* __restrict__ Wp,
                              float* __restrict__ Y) {
    __shared__ float xs[64][128];
    __shared__ float ssc[64];
    const int tx = threadIdx.x, ty = threadIdx.y;
    const int row0 = blockIdx.x * 64;
    const int tid = ty * 40 + tx;

    if (tid < 64) {
        int gr = row0 + tid;
        int d = 1;
        if (gr < NN) { d = g_deg_out[gr]; if (d < 1) d = 1; }
        ssc[tid] = rsqrtf((float)d);
    }
    __syncthreads();

    for (int i = tid; i < 64 * 32; i += 320) {
        int r = i >> 5, k4 = i & 31;
        int gr = row0 + r;
        float4 v = reinterpret_cast<const float4*>(X + (size_t)gr * 128)[k4];
        float s = ssc[r];
        v.x *= s; v.y *= s; v.z *= s; v.w *= s;
        reinterpret_cast<float4*>(&xs[r][0])[k4] = v;
    }
    __syncthreads();

    unsigned long long acc[8];
#pragma unroll
    for (int r = 0; r < 8; r++) acc[r] = 0ull;

#pragma unroll 4
    for (int q = 0; q < 32; q++) {
        unsigned long long w0 =
            *reinterpret_cast<const unsigned long long*>(&Wp[(2 * q) * 40 + tx]);
        unsigned long long w1 =
            *reinterpret_cast<const unsigned long long*>(&Wp[(2 * q + 1) * 40 + tx]);
#pragma unroll
        for (int r = 0; r < 8; r++) {
            ulonglong2 xv =
                *reinterpret_cast<const ulonglong2*>(&xs[ty * 8 + r][4 * q]);
            acc[r] = ffma2(xv.x, w0, acc[r]);
            acc[r] = ffma2(xv.y, w1, acc[r]);
        }
    }

#pragma unroll
    for (int r = 0; r < 8; r++) {
        int gr = row0 + ty * 8 + r;
        float2 f = *reinterpret_cast<float2*>(&acc[r]);
        Y[(size_t)gr * 40 + tx] = f.x + f.y;
    }
}

// ---------------- CSR aggregation, unroll-2 (warp per dst node) -------------
// sin = rsqrt(max(deg_in,1)) computed inline from rowptr diff.
template <bool RELU>
__global__ void agg128_kernel(const float* __restrict__ hw,
                              const float* __restrict__ bias,
                              float* __restrict__ out) {
    int w = (blockIdx.x * blockDim.x + threadIdx.x) >> 5;
    int lane = threadIdx.x & 31;
    if (w >= NN) return;
    int e0 = g_rowptr[w], e1 = g_rowptr[w + 1];
    float4 a0 = make_float4(0.f, 0.f, 0.f, 0.f);
    float4 a1 = make_float4(0.f, 0.f, 0.f, 0.f);
    for (int base = e0; base < e1; base += 32) {
        int cnt = e1 - base; if (cnt > 32) cnt = 32;
        int myi = (lane < cnt) ? g_esrc[base + lane] : 0;
        int j = 0;
        for (; j + 1 < cnt; j += 2) {
            int s0 = __shfl_sync(0xffffffffu, myi, j);
            int s1 = __shfl_sync(0xffffffffu, myi, j + 1);
            const float4 v0 = *reinterpret_cast<const float4*>(hw + (size_t)s0 * 128 + lane * 4);
            const float4 v1 = *reinterpret_cast<const float4*>(hw + (size_t)s1 * 128 + lane * 4);
            a0.x += v0.x; a0.y += v0.y; a0.z += v0.z; a0.w += v0.w;
            a1.x += v1.x; a1.y += v1.y; a1.z += v1.z; a1.w += v1.w;
        }
        if (j < cnt) {
            int s0 = __shfl_sync(0xffffffffu, myi, j);
            const float4 v0 = *reinterpret_cast<const float4*>(hw + (size_t)s0 * 128 + lane * 4);
            a0.x += v0.x; a0.y += v0.y; a0.z += v0.z; a0.w += v0.w;
        }
    }
    int deg = e1 - e0; if (deg < 1) deg = 1;
    float sc = rsqrtf((float)deg);
    float4 bb = *reinterpret_cast<const float4*>(bias + lane * 4);
    float4 r;
    r.x = (a0.x + a1.x) * sc + bb.x;
    r.y = (a0.y + a1.y) * sc + bb.y;
    r.z = (a0.z + a1.z) * sc + bb.z;
    r.w = (a0.w + a1.w) * sc + bb.w;
    if (RELU) {
        r.x = fmaxf(r.x, 0.f); r.y = fmaxf(r.y, 0.f);
        r.z = fmaxf(r.z, 0.f); r.w = fmaxf(r.w, 0.f);
    }
    *reinterpret_cast<float4*>(out + (size_t)w * 128 + lane * 4) = r;
}

__global__ void agg40_kernel(const float* __restrict__ hw,
                             const float* __restrict__ bias,
                             float* __restrict__ out) {
    int w = (blockIdx.x * blockDim.x + threadIdx.x) >> 5;
    int lane = threadIdx.x & 31;
    if (w >= NN) return;
    int e0 = g_rowptr[w], e1 = g_rowptr[w + 1];
    float4 a0 = make_float4(0.f, 0.f, 0.f, 0.f);
    float4 a1 = make_float4(0.f, 0.f, 0.f, 0.f);
    for (int base = e0; base < e1; base += 32) {
        int cnt = e1 - base; if (cnt > 32) cnt = 32;
        int myi = (lane < cnt) ? g_esrc[base + lane] : 0;
        int j = 0;
        for (; j + 1 < cnt; j += 2) {
            int s0 = __shfl_sync(0xffffffffu, myi, j);
            int s1 = __shfl_sync(0xffffffffu, myi, j + 1);
            if (lane < 10) {
                const float4 v0 = *reinterpret_cast<const float4*>(hw + (size_t)s0 * 40 + lane * 4);
                const float4 v1 = *reinterpret_cast<const float4*>(hw + (size_t)s1 * 40 + lane * 4);
                a0.x += v0.x; a0.y += v0.y; a0.z += v0.z; a0.w += v0.w;
                a1.x += v1.x; a1.y += v1.y; a1.z += v1.z; a1.w += v1.w;
            }
        }
        if (j < cnt) {
            int s0 = __shfl_sync(0xffffffffu, myi, j);
            if (lane < 10) {
                const float4 v0 = *reinterpret_cast<const float4*>(hw + (size_t)s0 * 40 + lane * 4);
                a0.x += v0.x; a0.y += v0.y; a0.z += v0.z; a0.w += v0.w;
            }
        }
    }
    if (lane < 10) {
        int deg = e1 - e0; if (deg < 1) deg = 1;
        float sc = rsqrtf((float)deg);
        float4 bb = *reinterpret_cast<const float4*>(bias + lane * 4);
        float4 r;
        r.x = (a0.x + a1.x) * sc + bb.x;
        r.y = (a0.y + a1.y) * sc + bb.y;
        r.z = (a0.z + a1.z) * sc + bb.z;
        r.w = (a0.w + a1.w) * sc + bb.w;
        *reinterpret_cast<float4*>(out + (size_t)w * 40 + lane * 4) = r;
    }
}

// ---------------- launch (R11-proven fork pattern) ---------------------------
extern "C" void kernel_launch(void* const* d_in, const int* in_sizes, int n_in,
                              void* d_out, int out_size) {
    (void)in_sizes; (void)n_in; (void)out_size;
    const float* feat = (const float*)d_in[0];
    const int*   src  = (const int*)  d_in[1];
    const int*   dst  = (const int*)  d_in[2];
    const float* W0   = (const float*)d_in[3];
    const float* b0   = (const float*)d_in[4];
    const float* W1   = (const float*)d_in[5];
    const float* b1   = (const float*)d_in[6];
    const float* W2   = (const float*)d_in[7];
    const float* b2   = (const float*)d_in[8];
    float* out = (float*)d_out;

    float *bufA, *bufB, *buf40;
    float4 *wA0, *wB0, *wA1, *wB1;
    float2 *wp2;
    cudaGetSymbolAddress((void**)&bufA, g_bufA);
    cudaGetSymbolAddress((void**)&bufB, g_bufB);
    cudaGetSymbolAddress((void**)&buf40, g_buf40);
    cudaGetSymbolAddress((void**)&wA0, g_wA0);
    cudaGetSymbolAddress((void**)&wB0, g_wB0);
    cudaGetSymbolAddress((void**)&wA1, g_wA1);
    cudaGetSymbolAddress((void**)&wB1, g_wB1);
    cudaGetSymbolAddress((void**)&wp2, g_wp2);

    static cudaStream_t s2 = nullptr;
    static cudaEvent_t evFork = nullptr, evCSR = nullptr;
    if (s2 == nullptr) {
        cudaStreamCreateWithFlags(&s2, cudaStreamNonBlocking);
        cudaEventCreateWithFlags(&evFork, cudaEventDisableTiming);
        cudaEventCreateWithFlags(&evCSR, cudaEventDisableTiming);
    }

    const int TB = 256;
    const int G128 = (NN + 63) / 64;                // 1563
    const int AGG  = (NN * 32 + TB - 1) / TB;       // 12500
    const int E4   = (NE / 4 + TB - 1) / TB;        // 1563
    const dim3 GB(32, 8);

    // main: pack weights + zero degrees, then histogram
    k_pack_zero<<<(NN + TB - 1) / TB, TB>>>(W0, W1, W2);
    k_count    <<<E4, TB>>>((const int4*)src, (const int4*)dst);
    cudaEventRecord(evFork, 0);

    // side (forked from capture stream): CSR scan + fill hide under gemm0
    cudaStreamWaitEvent(s2, evFork, 0);
    k_chunksum  <<<NB_SCAN, 512, 0, s2>>>();
    k_scanblocks<<<1, 256, 0, s2>>>();
    k_scanchunks<<<NB_SCAN, 512, 0, s2>>>();
    k_fill      <<<E4, TB, 0, s2>>>((const int4*)src, (const int4*)dst);
    cudaEventRecord(evCSR, s2);

    // main: layer-0 GEMM (feat -> A); needs pack + deg_out (both done)
    gemm128_kernel<true><<<G128, GB>>>(feat, wA0, wB0, bufA);

    // join, then serial ladder
    cudaStreamWaitEvent(0, evCSR, 0);
    agg128_kernel<true><<<AGG, TB>>>(bufA, b0, bufB);
    gemm128_kernel<false><<<G128, GB>>>(bufB, wA1, wB1, bufA);
    agg128_kernel<true><<<AGG, TB>>>(bufA, b1, bufB);
    gemm40_kernel <<<G128, dim3(40, 8)>>>(bufB, wp2, buf40);
    agg40_kernel  <<<AGG, TB>>>(buf40, b2, out);
}